// round 1
// baseline (speedup 1.0000x reference)
#include <cuda_runtime.h>
#include <cuda_bf16.h>
#include <cstdint>

// Problem dims (fixed for this dataset entry)
#define NE 8
#define NH 1024
#define NI 2048
#define NT 1024

// ---------------- device scratch (no allocations allowed) ----------------
__device__ int   g_counts[NE];
__device__ int   g_tok[NE * NT];
__device__ float g_gate[NE * NT];
__device__ float g_act[(size_t)NE * NT * NI];   // 64 MB fp32 activations

// ---------------- helpers ----------------
__device__ __forceinline__ float f2tf32(float x) {
    uint32_t u;
    asm("cvt.rna.tf32.f32 %0, %1;" : "=r"(u) : "f"(x));
    return __uint_as_float(u);
}

__device__ __forceinline__ void mma8(float* c, const uint32_t* a, const uint32_t* b) {
    asm volatile(
        "mma.sync.aligned.m16n8k8.row.col.f32.tf32.tf32.f32 "
        "{%0,%1,%2,%3}, {%4,%5,%6,%7}, {%8,%9}, {%0,%1,%2,%3};\n"
        : "+f"(c[0]), "+f"(c[1]), "+f"(c[2]), "+f"(c[3])
        : "r"(a[0]), "r"(a[1]), "r"(a[2]), "r"(a[3]), "r"(b[0]), "r"(b[1]));
}

// ---------------- kernel 0: zero output + counts ----------------
__global__ void zero_kernel(float* __restrict__ out) {
    int i = blockIdx.x * 256 + threadIdx.x;
    if (i < NT * NH) out[i] = 0.f;
    if (i < NE) g_counts[i] = 0;
}

// ---------------- kernel 1: router (softmax top-2 -> buckets) ----------------
__global__ void router_kernel(const float* __restrict__ logits) {
    int t = blockIdx.x * 256 + threadIdx.x;
    if (t >= NT) return;
    float b0 = -1e30f, b1 = -1e30f;
    int i0 = 0, i1 = 0;
#pragma unroll
    for (int ei = 0; ei < NE; ++ei) {
        float l = logits[t * NE + ei];
        if (l > b0) { b1 = b0; i1 = i0; b0 = l; i0 = ei; }
        else if (l > b1) { b1 = l; i1 = ei; }
    }
    // softmax denominators cancel: w0 = 1/(1+exp(l1-l0))
    float w0 = 1.f / (1.f + expf(b1 - b0));
    float w1 = 1.f - w0;
    int s0 = atomicAdd(&g_counts[i0], 1);
    g_tok[i0 * NT + s0] = t;  g_gate[i0 * NT + s0] = w0;
    int s1 = atomicAdd(&g_counts[i1], 1);
    g_tok[i1 * NT + s1] = t;  g_gate[i1 * NT + s1] = w1;
}

// ---------------- kernel 2: GEMM1 + fused SwiGLU ----------------
// Per CTA: BM=128 gathered token rows x BN=64 intermediate cols; computes BOTH
// glu (rows [0,2048)) and lin (rows [2048,4096)) tiles, applies activation,
// writes act[e][slot][n] fp32. K = NH = 1024, BK=32.
__global__ __launch_bounds__(256, 2)
void gemm1_kernel(const float* __restrict__ x, const float* __restrict__ w13,
                  const float* __restrict__ b13) {
    const int e   = blockIdx.z;
    const int cnt = g_counts[e];
    const int m0  = blockIdx.y * 128;
    if (m0 >= cnt) return;
    const int n0  = blockIdx.x * 64;

    __shared__ float sA[128][36];
    __shared__ float sB[2][64][36];
    __shared__ int   sTok[128];

    const int tid  = threadIdx.x;
    const int wid  = tid >> 5, lane = tid & 31;
    const int lr   = lane >> 2, lc = lane & 3;
    const int wm   = (wid & 3) * 32, wn = (wid >> 2) * 32;

    if (tid < 128) {
        int slot = m0 + tid;
        sTok[tid] = (slot < cnt) ? g_tok[e * NT + slot] : -1;
    }
    __syncthreads();

    float acc[2][2][4][4];
#pragma unroll
    for (int h = 0; h < 2; ++h)
#pragma unroll
        for (int mt = 0; mt < 2; ++mt)
#pragma unroll
            for (int nt = 0; nt < 4; ++nt)
#pragma unroll
                for (int i = 0; i < 4; ++i) acc[h][mt][nt][i] = 0.f;

#pragma unroll 1
    for (int k0 = 0; k0 < NH; k0 += 32) {
        // load A tile (gathered token rows), tf32-convert
#pragma unroll
        for (int it = 0; it < 4; ++it) {
            int i4 = tid + it * 256;          // 0..1023 float4s
            int row = i4 >> 3, c4 = (i4 & 7) * 4;
            int tk = sTok[row];
            float4 v = make_float4(0.f, 0.f, 0.f, 0.f);
            if (tk >= 0) v = *(const float4*)(x + (size_t)tk * NH + k0 + c4);
            sA[row][c4 + 0] = f2tf32(v.x);
            sA[row][c4 + 1] = f2tf32(v.y);
            sA[row][c4 + 2] = f2tf32(v.z);
            sA[row][c4 + 3] = f2tf32(v.w);
        }
        // load B tiles (glu half + lin half)
#pragma unroll
        for (int it = 0; it < 4; ++it) {
            int i4 = tid + it * 256;          // 0..1023
            int hh = i4 >> 9, rr = (i4 >> 3) & 63, c4 = (i4 & 7) * 4;
            const float4 v = *(const float4*)(
                w13 + ((size_t)e * 4096 + hh * 2048 + n0 + rr) * NH + k0 + c4);
            sB[hh][rr][c4 + 0] = f2tf32(v.x);
            sB[hh][rr][c4 + 1] = f2tf32(v.y);
            sB[hh][rr][c4 + 2] = f2tf32(v.z);
            sB[hh][rr][c4 + 3] = f2tf32(v.w);
        }
        __syncthreads();

#pragma unroll
        for (int kk = 0; kk < 32; kk += 8) {
            uint32_t a[2][4];
#pragma unroll
            for (int mt = 0; mt < 2; ++mt) {
                int r = wm + mt * 16 + lr;
                a[mt][0] = __float_as_uint(sA[r][kk + lc]);
                a[mt][1] = __float_as_uint(sA[r + 8][kk + lc]);
                a[mt][2] = __float_as_uint(sA[r][kk + 4 + lc]);
                a[mt][3] = __float_as_uint(sA[r + 8][kk + 4 + lc]);
            }
            uint32_t b[2][4][2];
#pragma unroll
            for (int hh = 0; hh < 2; ++hh)
#pragma unroll
                for (int nt = 0; nt < 4; ++nt) {
                    int cc = wn + nt * 8 + lr;
                    b[hh][nt][0] = __float_as_uint(sB[hh][cc][kk + lc]);
                    b[hh][nt][1] = __float_as_uint(sB[hh][cc][kk + 4 + lc]);
                }
#pragma unroll
            for (int hh = 0; hh < 2; ++hh)
#pragma unroll
                for (int mt = 0; mt < 2; ++mt)
#pragma unroll
                    for (int nt = 0; nt < 4; ++nt)
                        mma8(acc[hh][mt][nt], a[mt], b[hh][nt]);
        }
        __syncthreads();
    }

    // epilogue: act = glu*sigmoid(1.702*glu)*(lin+1), with biases
#pragma unroll
    for (int mt = 0; mt < 2; ++mt)
#pragma unroll
        for (int i = 0; i < 2; ++i) {
            int r = wm + mt * 16 + lr + i * 8;
            int slot = m0 + r;
            if (slot >= cnt) continue;
            float* arow = g_act + ((size_t)e * NT + slot) * NI + n0;
#pragma unroll
            for (int nt = 0; nt < 4; ++nt) {
#pragma unroll
                for (int j = 0; j < 2; ++j) {
                    int col = wn + nt * 8 + lc * 2 + j;
                    float glu = acc[0][mt][nt][i * 2 + j] + b13[e * 4096 + n0 + col];
                    float lin = acc[1][mt][nt][i * 2 + j] + b13[e * 4096 + 2048 + n0 + col];
                    float sg  = 1.f / (1.f + __expf(-1.702f * glu));
                    arow[col] = glu * sg * (lin + 1.0f);
                }
            }
        }
}

// ---------------- kernel 3: GEMM2 + gated scatter ----------------
// y[slot, hcol] = act[slot,:] . w2[e,hcol,:] + b2 ; out[token] += gate * y
__global__ __launch_bounds__(256, 2)
void gemm2_kernel(const float* __restrict__ w2, const float* __restrict__ b2,
                  float* __restrict__ out) {
    const int e   = blockIdx.z;
    const int cnt = g_counts[e];
    const int m0  = blockIdx.y * 128;
    if (m0 >= cnt) return;
    const int n0  = blockIdx.x * 64;

    __shared__ float sA[128][36];
    __shared__ float sB[64][36];
    __shared__ int   sTok[128];
    __shared__ float sG[128];

    const int tid  = threadIdx.x;
    const int wid  = tid >> 5, lane = tid & 31;
    const int lr   = lane >> 2, lc = lane & 3;
    const int wm   = (wid & 3) * 32, wn = (wid >> 2) * 32;

    if (tid < 128) {
        int slot = m0 + tid;
        sTok[tid] = (slot < cnt) ? g_tok[e * NT + slot] : -1;
        sG[tid]   = (slot < cnt) ? g_gate[e * NT + slot] : 0.f;
    }
    __syncthreads();

    float acc[2][4][4];
#pragma unroll
    for (int mt = 0; mt < 2; ++mt)
#pragma unroll
        for (int nt = 0; nt < 4; ++nt)
#pragma unroll
            for (int i = 0; i < 4; ++i) acc[mt][nt][i] = 0.f;

#pragma unroll 1
    for (int k0 = 0; k0 < NI; k0 += 32) {
#pragma unroll
        for (int it = 0; it < 4; ++it) {           // A: 128 rows x 8 float4
            int i4 = tid + it * 256;
            int row = i4 >> 3, c4 = (i4 & 7) * 4;
            int slot = m0 + row;
            float4 v = make_float4(0.f, 0.f, 0.f, 0.f);
            if (slot < cnt)
                v = *(const float4*)(g_act + ((size_t)e * NT + slot) * NI + k0 + c4);
            sA[row][c4 + 0] = f2tf32(v.x);
            sA[row][c4 + 1] = f2tf32(v.y);
            sA[row][c4 + 2] = f2tf32(v.z);
            sA[row][c4 + 3] = f2tf32(v.w);
        }
#pragma unroll
        for (int it = 0; it < 2; ++it) {           // B: 64 rows x 8 float4
            int i4 = tid + it * 256;
            int rr = i4 >> 3, c4 = (i4 & 7) * 4;
            const float4 v = *(const float4*)(
                w2 + ((size_t)e * NH + n0 + rr) * NI + k0 + c4);
            sB[rr][c4 + 0] = f2tf32(v.x);
            sB[rr][c4 + 1] = f2tf32(v.y);
            sB[rr][c4 + 2] = f2tf32(v.z);
            sB[rr][c4 + 3] = f2tf32(v.w);
        }
        __syncthreads();

#pragma unroll
        for (int kk = 0; kk < 32; kk += 8) {
            uint32_t a[2][4];
#pragma unroll
            for (int mt = 0; mt < 2; ++mt) {
                int r = wm + mt * 16 + lr;
                a[mt][0] = __float_as_uint(sA[r][kk + lc]);
                a[mt][1] = __float_as_uint(sA[r + 8][kk + lc]);
                a[mt][2] = __float_as_uint(sA[r][kk + 4 + lc]);
                a[mt][3] = __float_as_uint(sA[r + 8][kk + 4 + lc]);
            }
            uint32_t b[4][2];
#pragma unroll
            for (int nt = 0; nt < 4; ++nt) {
                int cc = wn + nt * 8 + lr;
                b[nt][0] = __float_as_uint(sB[cc][kk + lc]);
                b[nt][1] = __float_as_uint(sB[cc][kk + 4 + lc]);
            }
#pragma unroll
            for (int mt = 0; mt < 2; ++mt)
#pragma unroll
                for (int nt = 0; nt < 4; ++nt)
                    mma8(acc[mt][nt], a[mt], b[nt]);
        }
        __syncthreads();
    }

    // epilogue: gated scatter-add into out (exactly 2 contributions/token -> commutative)
#pragma unroll
    for (int mt = 0; mt < 2; ++mt)
#pragma unroll
        for (int i = 0; i < 2; ++i) {
            int r = wm + mt * 16 + lr + i * 8;
            int slot = m0 + r;
            if (slot >= cnt) continue;
            int tk = sTok[r];
            float g = sG[r];
            float* orow = out + (size_t)tk * NH + n0;
#pragma unroll
            for (int nt = 0; nt < 4; ++nt) {
#pragma unroll
                for (int j = 0; j < 2; ++j) {
                    int col = wn + nt * 8 + lc * 2 + j;
                    float y = acc[mt][nt][i * 2 + j] + b2[e * NH + n0 + col];
                    atomicAdd(&orow[col], g * y);
                }
            }
        }
}

// ---------------- host entry ----------------
extern "C" void kernel_launch(void* const* d_in, const int* in_sizes, int n_in,
                              void* d_out, int out_size) {
    const float* x      = (const float*)d_in[0];
    const float* logits = (const float*)d_in[1];
    const float* w13    = (const float*)d_in[2];
    const float* w2     = (const float*)d_in[3];
    const float* b13    = (const float*)d_in[4];
    const float* b2     = (const float*)d_in[5];
    float* out          = (float*)d_out;

    zero_kernel<<<(NT * NH + 255) / 256, 256>>>(out);
    router_kernel<<<(NT + 255) / 256, 256>>>(logits);
    gemm1_kernel<<<dim3(NI / 64, NT / 128, NE), 256>>>(x, w13, b13);
    gemm2_kernel<<<dim3(NH / 64, NT / 128, NE), 256>>>(w2, b2, out);
}

// round 3
// speedup vs baseline: 2.1009x; 2.1009x over previous
#include <cuda_runtime.h>
#include <cuda_fp16.h>
#include <cstdint>

#define NE 8
#define NH 1024
#define NI 2048
#define NT 1024

// ---------------- device scratch (no allocations allowed) ----------------
__device__ int    g_counts[NE];
__device__ int    g_tok[NE * NT];
__device__ float  g_gate[NE * NT];
__device__ __half g_x16[(size_t)NT * NH];          // 2 MB
__device__ __half g_act[(size_t)NE * NT * NI];     // 33.5 MB

// ---------------- PTX helpers (base-PTX only: sm_100 safe) ----------------
__device__ __forceinline__ uint32_t smem_u32(const void* p) {
    uint32_t a;
    asm("{ .reg .u64 t; cvta.to.shared.u64 t, %1; cvt.u32.u64 %0, t; }" : "=r"(a) : "l"(p));
    return a;
}
__device__ __forceinline__ void ldm4(uint32_t* r, uint32_t addr) {
    asm volatile("ldmatrix.sync.aligned.m8n8.x4.shared.b16 {%0,%1,%2,%3}, [%4];"
                 : "=r"(r[0]), "=r"(r[1]), "=r"(r[2]), "=r"(r[3]) : "r"(addr));
}
__device__ __forceinline__ void mma16(float* c, const uint32_t* a, const uint32_t* b) {
    asm volatile(
        "mma.sync.aligned.m16n8k16.row.col.f32.f16.f16.f32 "
        "{%0,%1,%2,%3},{%4,%5,%6,%7},{%8,%9},{%0,%1,%2,%3};"
        : "+f"(c[0]), "+f"(c[1]), "+f"(c[2]), "+f"(c[3])
        : "r"(a[0]), "r"(a[1]), "r"(a[2]), "r"(a[3]), "r"(b[0]), "r"(b[1]));
}
__device__ __forceinline__ void cpa16(uint32_t dst, const void* src) {
    asm volatile("cp.async.cg.shared.global [%0], [%1], 16;" :: "r"(dst), "l"(src));
}
__device__ __forceinline__ void cp_commit() { asm volatile("cp.async.commit_group;"); }
template <int N> __device__ __forceinline__ void cp_wait() {
    asm volatile("cp.async.wait_group %0;" :: "n"(N));
}
__device__ __forceinline__ uint32_t pkh2(float a, float b) {
    __half2 t = __floats2half2_rn(a, b);
    return *reinterpret_cast<uint32_t*>(&t);
}

// smem tile geometry: 128 rows x 64 fp16 (=128B), padded row stride 144B
#define RSTRIDE 144
#define TILE_B  (128 * RSTRIDE)           // 18432
#define OFF_A(b) (1024 + (b) * 2 * TILE_B)
#define OFF_B(b) (1024 + (b) * 2 * TILE_B + TILE_B)
#define SMEM_TOT (1024 + 4 * TILE_B)      // 74752

// ---------------- kernel 0: zero out + counts, convert x -> fp16 ----------------
__global__ void prep_kernel(const float* __restrict__ x, float* __restrict__ out) {
    int i = blockIdx.x * 256 + threadIdx.x;
    if (i < NT * NH) { out[i] = 0.f; g_x16[i] = __float2half_rn(x[i]); }
    if (i < NE) g_counts[i] = 0;
}

// ---------------- kernel 1: router ----------------
__global__ void router_kernel(const float* __restrict__ logits) {
    int t = blockIdx.x * 256 + threadIdx.x;
    if (t >= NT) return;
    float b0 = -1e30f, b1 = -1e30f;
    int i0 = 0, i1 = 0;
#pragma unroll
    for (int ei = 0; ei < NE; ++ei) {
        float l = logits[t * NE + ei];
        if (l > b0) { b1 = b0; i1 = i0; b0 = l; i0 = ei; }
        else if (l > b1) { b1 = l; i1 = ei; }
    }
    float w0 = 1.f / (1.f + expf(b1 - b0));
    float w1 = 1.f - w0;
    int s0 = atomicAdd(&g_counts[i0], 1);
    g_tok[i0 * NT + s0] = t;  g_gate[i0 * NT + s0] = w0;
    int s1 = atomicAdd(&g_counts[i1], 1);
    g_tok[i1 * NT + s1] = t;  g_gate[i1 * NT + s1] = w1;
}

// ---------------- GEMM1: h = x @ w13^T + fused SwiGLU -> g_act (fp16) ----------------
// CTA: 128 gathered token rows x 64 intermediate cols (glu & lin both in-tile).
// A (x fp16) via cp.async; B (w13 fp32) via LDG->cvt->STS; BK=64, 2 stages.
__global__ __launch_bounds__(256, 2)
void gemm1_k(const float* __restrict__ w13, const float* __restrict__ b13) {
    const int e   = blockIdx.z;
    const int cnt = g_counts[e];
    const int m0  = blockIdx.y * 128;
    if (m0 >= cnt) return;
    const int n0i = blockIdx.x * 64;

    extern __shared__ char sm[];
    const uint32_t smb = smem_u32(sm);
    const int tid = threadIdx.x, wid = tid >> 5, lane = tid & 31;
    const int lr = lane >> 2, lc = lane & 3;
    const int wm = (wid & 3) * 32, wn = (wid >> 2) * 32;
    int* sTok = (int*)sm;

    if (tid < 128) { int s = m0 + tid; sTok[tid] = (s < cnt) ? g_tok[e * NT + s] : 0; }
    __syncthreads();

    float acc[2][8][4];
#pragma unroll
    for (int mt = 0; mt < 2; ++mt)
#pragma unroll
        for (int nt = 0; nt < 8; ++nt)
#pragma unroll
            for (int i = 0; i < 4; ++i) acc[mt][nt][i] = 0.f;

    // per-thread loader coords
    const int ar = tid >> 3,  ac = tid & 7;     // A: +i*32 rows, chunk ac (16B)
    const int br = tid >> 4,  bc = tid & 15;    // B: +i*16 rows, float4 chunk bc

    // lane-fixed ldmatrix offsets
    const uint32_t aoff = (uint32_t)((wm + (lane & 15)) * RSTRIDE + (lane >> 4) * 16);
    const uint32_t boff = (uint32_t)(((lane & 7) + ((lane >> 4) << 3)) * RSTRIDE
                                     + ((lane >> 3) & 1) * 16);

    float4 b4[8];
    // ---- prologue: LDG B(0), cp.async A(0)
#pragma unroll
    for (int i = 0; i < 8; ++i) {
        int r = br + i * 16;
        int grow = (r < 64) ? (n0i + r) : (2048 + n0i + r - 64);
        b4[i] = *(const float4*)(w13 + ((size_t)e * 4096 + grow) * NH + bc * 4);
    }
#pragma unroll
    for (int i = 0; i < 4; ++i) {
        int r = ar + i * 32;
        cpa16(smb + OFF_A(0) + r * RSTRIDE + ac * 16,
              g_x16 + (size_t)sTok[r] * NH + ac * 8);
    }
    cp_commit();

#pragma unroll 1
    for (int s = 0; s < 16; ++s) {
        const int cur = s & 1;
        const uint32_t stA = OFF_A(cur), stB = OFF_B(cur);
        // STS B(s)
#pragma unroll
        for (int i = 0; i < 8; ++i) {
            int r = br + i * 16;
            uint2 p = make_uint2(pkh2(b4[i].x, b4[i].y), pkh2(b4[i].z, b4[i].w));
            *(uint2*)(sm + stB + r * RSTRIDE + bc * 8) = p;
        }
        if (s < 15) {
            const int k0n = (s + 1) * 64;
#pragma unroll
            for (int i = 0; i < 4; ++i) {
                int r = ar + i * 32;
                cpa16(smb + OFF_A(cur ^ 1) + r * RSTRIDE + ac * 16,
                      g_x16 + (size_t)sTok[r] * NH + k0n + ac * 8);
            }
            cp_commit();
            cp_wait<1>();
        } else {
            cp_wait<0>();
        }
        __syncthreads();

        // ---- compute stage cur
#pragma unroll
        for (int k16 = 0; k16 < 4; ++k16) {
            uint32_t a[2][4];
            uint32_t abase = smb + stA + aoff + k16 * 32;
            ldm4(a[0], abase);
            ldm4(a[1], abase + 16 * RSTRIDE);
#pragma unroll
            for (int ntp = 0; ntp < 4; ++ntp) {
                int browoff = ((ntp >= 2) ? 64 : 0) + wn + ((ntp & 1) << 4);
                uint32_t b[4];
                ldm4(b, smb + stB + boff + browoff * RSTRIDE + k16 * 32);
                mma16(acc[0][ntp * 2],     a[0], b);
                mma16(acc[1][ntp * 2],     a[1], b);
                mma16(acc[0][ntp * 2 + 1], a[0], b + 2);
                mma16(acc[1][ntp * 2 + 1], a[1], b + 2);
            }
        }
        if (s < 15) {
            const int k0n = (s + 1) * 64;
#pragma unroll
            for (int i = 0; i < 8; ++i) {
                int r = br + i * 16;
                int grow = (r < 64) ? (n0i + r) : (2048 + n0i + r - 64);
                b4[i] = *(const float4*)(w13 + ((size_t)e * 4096 + grow) * NH + k0n + bc * 4);
            }
        }
        __syncthreads();
    }

    // ---- epilogue: SwiGLU in registers, stage act tile in smem, coalesced store
    const float* bg = b13 + (size_t)e * 4096 + n0i;
    const float* bl = b13 + (size_t)e * 4096 + 2048 + n0i;
#pragma unroll
    for (int mt = 0; mt < 2; ++mt)
#pragma unroll
        for (int nt = 0; nt < 4; ++nt)
#pragma unroll
            for (int i = 0; i < 2; ++i) {
                int row = wm + mt * 16 + lr + i * 8;
                int col = wn + nt * 8 + lc * 2;
                float g0 = acc[mt][nt][i * 2 + 0] + bg[col];
                float g1 = acc[mt][nt][i * 2 + 1] + bg[col + 1];
                float l0 = acc[mt][nt + 4][i * 2 + 0] + bl[col];
                float l1 = acc[mt][nt + 4][i * 2 + 1] + bl[col + 1];
                float a0 = g0 * (1.f / (1.f + __expf(-1.702f * g0))) * (l0 + 1.0f);
                float a1 = g1 * (1.f / (1.f + __expf(-1.702f * g1))) * (l1 + 1.0f);
                *(uint32_t*)(sm + 1024 + row * RSTRIDE + col * 2) = pkh2(a0, a1);
            }
    __syncthreads();
#pragma unroll
    for (int i = 0; i < 4; ++i) {
        int idx = i * 256 + tid;
        int r = idx >> 3, c = idx & 7;
        int slot = m0 + r;
        if (slot < cnt) {
            uint4 v = *(uint4*)(sm + 1024 + r * RSTRIDE + c * 16);
            *(uint4*)(g_act + ((size_t)e * NT + slot) * NI + n0i * 1 + c * 8
                      + ((size_t)0)) = v;  // row base: (e*NT+slot)*NI + n0i
        }
    }
}

// ---------------- GEMM2: y = act @ w2^T, gated atomic scatter ----------------
// CTA: 128 slots x 128 out cols. A (act fp16) via cp.async; B (w2 fp32) LDG->STS.
__global__ __launch_bounds__(256, 2)
void gemm2_k(const float* __restrict__ w2, const float* __restrict__ b2,
             float* __restrict__ out) {
    const int e   = blockIdx.z;
    const int cnt = g_counts[e];
    const int m0  = blockIdx.y * 128;
    if (m0 >= cnt) return;
    const int n0  = blockIdx.x * 128;

    extern __shared__ char sm[];
    const uint32_t smb = smem_u32(sm);
    const int tid = threadIdx.x, wid = tid >> 5, lane = tid & 31;
    const int lr = lane >> 2, lc = lane & 3;
    const int wm = (wid & 3) * 32, wn = (wid >> 2) * 64;
    int*   sTok = (int*)sm;
    float* sG   = (float*)(sm + 512);

    if (tid < 128) {
        int slot = m0 + tid;
        sTok[tid] = (slot < cnt) ? g_tok[e * NT + slot] : 0;
        sG[tid]   = (slot < cnt) ? g_gate[e * NT + slot] : 0.f;
    }
    __syncthreads();

    float acc[2][8][4];
#pragma unroll
    for (int mt = 0; mt < 2; ++mt)
#pragma unroll
        for (int nt = 0; nt < 8; ++nt)
#pragma unroll
            for (int i = 0; i < 4; ++i) acc[mt][nt][i] = 0.f;

    const int ar = tid >> 3,  ac = tid & 7;
    const int br = tid >> 4,  bc = tid & 15;
    const uint32_t aoff = (uint32_t)((wm + (lane & 15)) * RSTRIDE + (lane >> 4) * 16);
    const uint32_t boff = (uint32_t)(((lane & 7) + ((lane >> 4) << 3)) * RSTRIDE
                                     + ((lane >> 3) & 1) * 16);

    float4 b4[8];
#pragma unroll
    for (int i = 0; i < 8; ++i) {
        int r = br + i * 16;
        b4[i] = *(const float4*)(w2 + ((size_t)e * NH + n0 + r) * NI + bc * 4);
    }
#pragma unroll
    for (int i = 0; i < 4; ++i) {
        int r = ar + i * 32;
        cpa16(smb + OFF_A(0) + r * RSTRIDE + ac * 16,
              g_act + ((size_t)e * NT + m0 + r) * NI + ac * 8);
    }
    cp_commit();

#pragma unroll 1
    for (int s = 0; s < 32; ++s) {
        const int cur = s & 1;
        const uint32_t stA = OFF_A(cur), stB = OFF_B(cur);
#pragma unroll
        for (int i = 0; i < 8; ++i) {
            int r = br + i * 16;
            uint2 p = make_uint2(pkh2(b4[i].x, b4[i].y), pkh2(b4[i].z, b4[i].w));
            *(uint2*)(sm + stB + r * RSTRIDE + bc * 8) = p;
        }
        if (s < 31) {
            const int k0n = (s + 1) * 64;
#pragma unroll
            for (int i = 0; i < 4; ++i) {
                int r = ar + i * 32;
                cpa16(smb + OFF_A(cur ^ 1) + r * RSTRIDE + ac * 16,
                      g_act + ((size_t)e * NT + m0 + r) * NI + k0n + ac * 8);
            }
            cp_commit();
            cp_wait<1>();
        } else {
            cp_wait<0>();
        }
        __syncthreads();

#pragma unroll
        for (int k16 = 0; k16 < 4; ++k16) {
            uint32_t a[2][4];
            uint32_t abase = smb + stA + aoff + k16 * 32;
            ldm4(a[0], abase);
            ldm4(a[1], abase + 16 * RSTRIDE);
#pragma unroll
            for (int ntp = 0; ntp < 4; ++ntp) {
                uint32_t b[4];
                ldm4(b, smb + stB + boff + (wn + ntp * 16) * RSTRIDE + k16 * 32);
                mma16(acc[0][ntp * 2],     a[0], b);
                mma16(acc[1][ntp * 2],     a[1], b);
                mma16(acc[0][ntp * 2 + 1], a[0], b + 2);
                mma16(acc[1][ntp * 2 + 1], a[1], b + 2);
            }
        }
        if (s < 31) {
            const int k0n = (s + 1) * 64;
#pragma unroll
            for (int i = 0; i < 8; ++i) {
                int r = br + i * 16;
                b4[i] = *(const float4*)(w2 + ((size_t)e * NH + n0 + r) * NI + k0n + bc * 4);
            }
        }
        __syncthreads();
    }

    // epilogue: out[tok, n0+col] += gate * (acc + b2)
    const float* bb = b2 + (size_t)e * NH + n0;
#pragma unroll
    for (int mt = 0; mt < 2; ++mt)
#pragma unroll
        for (int i = 0; i < 2; ++i) {
            int row = wm + mt * 16 + lr + i * 8;
            int slot = m0 + row;
            if (slot >= cnt) continue;
            int tok = sTok[row];
            float gate = sG[row];
            float* orow = out + (size_t)tok * NH + n0;
#pragma unroll
            for (int nt = 0; nt < 8; ++nt) {
                int col = wn + nt * 8 + lc * 2;
                atomicAdd(orow + col,     gate * (acc[mt][nt][i * 2 + 0] + bb[col]));
                atomicAdd(orow + col + 1, gate * (acc[mt][nt][i * 2 + 1] + bb[col + 1]));
            }
        }
}

// ---------------- host entry ----------------
extern "C" void kernel_launch(void* const* d_in, const int* in_sizes, int n_in,
                              void* d_out, int out_size) {
    const float* x      = (const float*)d_in[0];
    const float* logits = (const float*)d_in[1];
    const float* w13    = (const float*)d_in[2];
    const float* w2     = (const float*)d_in[3];
    const float* b13    = (const float*)d_in[4];
    const float* b2     = (const float*)d_in[5];
    float* out          = (float*)d_out;

    static bool attr_done = false;
    if (!attr_done) {
        cudaFuncSetAttribute(gemm1_k, cudaFuncAttributeMaxDynamicSharedMemorySize, SMEM_TOT);
        cudaFuncSetAttribute(gemm2_k, cudaFuncAttributeMaxDynamicSharedMemorySize, SMEM_TOT);
        attr_done = true;
    }

    prep_kernel<<<(NT * NH + 255) / 256, 256>>>(x, out);
    router_kernel<<<(NT + 255) / 256, 256>>>(logits);
    gemm1_k<<<dim3(NI / 64, NT / 128, NE), 256, SMEM_TOT>>>(w13, b13);
    gemm2_k<<<dim3(NH / 128, NT / 128, NE), 256, SMEM_TOT>>>(w2, b2, out);
}

// round 4
// speedup vs baseline: 2.1580x; 1.0272x over previous
#include <cuda_runtime.h>
#include <cuda_fp16.h>
#include <cstdint>

#define NE 8
#define NH 1024
#define NI 2048
#define NT 1024

// ---------------- device scratch (no allocations allowed) ----------------
__device__ int    g_counts[NE];
__device__ int    g_tok[NE * NT];
__device__ float  g_gate[NE * NT];
__device__ __half g_x16[(size_t)NT * NH];          // 2 MB
__device__ __half g_act[(size_t)NE * NT * NI];     // 33.5 MB

// ---------------- PTX helpers (base-PTX only: sm_100 safe) ----------------
__device__ __forceinline__ uint32_t smem_u32(const void* p) {
    uint32_t a;
    asm("{ .reg .u64 t; cvta.to.shared.u64 t, %1; cvt.u32.u64 %0, t; }" : "=r"(a) : "l"(p));
    return a;
}
__device__ __forceinline__ void ldm4(uint32_t* r, uint32_t addr) {
    asm volatile("ldmatrix.sync.aligned.m8n8.x4.shared.b16 {%0,%1,%2,%3}, [%4];"
                 : "=r"(r[0]), "=r"(r[1]), "=r"(r[2]), "=r"(r[3]) : "r"(addr));
}
__device__ __forceinline__ void mma16(float* c, const uint32_t* a, const uint32_t* b) {
    asm volatile(
        "mma.sync.aligned.m16n8k16.row.col.f32.f16.f16.f32 "
        "{%0,%1,%2,%3},{%4,%5,%6,%7},{%8,%9},{%0,%1,%2,%3};"
        : "+f"(c[0]), "+f"(c[1]), "+f"(c[2]), "+f"(c[3])
        : "r"(a[0]), "r"(a[1]), "r"(a[2]), "r"(a[3]), "r"(b[0]), "r"(b[1]));
}
__device__ __forceinline__ void cpa16(uint32_t dst, const void* src) {
    asm volatile("cp.async.cg.shared.global [%0], [%1], 16;" :: "r"(dst), "l"(src));
}
__device__ __forceinline__ void cp_commit() { asm volatile("cp.async.commit_group;"); }
template <int N> __device__ __forceinline__ void cp_wait() {
    asm volatile("cp.async.wait_group %0;" :: "n"(N));
}
__device__ __forceinline__ uint32_t pkh2(float a, float b) {
    __half2 t = __floats2half2_rn(a, b);
    return *reinterpret_cast<uint32_t*>(&t);
}

// smem tile geometry: 128 rows x 64 fp16 (=128B), padded row stride 144B
#define RSTRIDE 144
#define TILE_B  (128 * RSTRIDE)           // 18432
#define OFF_A(b) (1024 + (b) * 2 * TILE_B)
#define OFF_B(b) (1024 + (b) * 2 * TILE_B + TILE_B)
#define SMEM_TOT (1024 + 4 * TILE_B)      // 74752

// ---------------- kernel 0: zero out + counts, convert x -> fp16 ----------------
__global__ void prep_kernel(const float* __restrict__ x, float* __restrict__ out) {
    int i = blockIdx.x * 256 + threadIdx.x;
    if (i < NT * NH) { out[i] = 0.f; g_x16[i] = __float2half_rn(x[i]); }
    if (i < NE) g_counts[i] = 0;
}

// ---------------- kernel 1: router ----------------
__global__ void router_kernel(const float* __restrict__ logits) {
    int t = blockIdx.x * 256 + threadIdx.x;
    if (t >= NT) return;
    float b0 = -1e30f, b1 = -1e30f;
    int i0 = 0, i1 = 0;
#pragma unroll
    for (int ei = 0; ei < NE; ++ei) {
        float l = logits[t * NE + ei];
        if (l > b0) { b1 = b0; i1 = i0; b0 = l; i0 = ei; }
        else if (l > b1) { b1 = l; i1 = ei; }
    }
    float w0 = 1.f / (1.f + expf(b1 - b0));
    float w1 = 1.f - w0;
    int s0 = atomicAdd(&g_counts[i0], 1);
    g_tok[i0 * NT + s0] = t;  g_gate[i0 * NT + s0] = w0;
    int s1 = atomicAdd(&g_counts[i1], 1);
    g_tok[i1 * NT + s1] = t;  g_gate[i1 * NT + s1] = w1;
}

// ---------------- GEMM1: h = x @ w13^T + fused SwiGLU -> g_act (fp16) ----------------
// CTA: 128 gathered token rows x 64 inter cols (glu & lin both in-tile).
// Single-barrier pipeline: writes target alt buffer while MMAs read cur.
__global__ __launch_bounds__(256, 2)
void gemm1_k(const float* __restrict__ w13, const float* __restrict__ b13) {
    const int e   = blockIdx.z;
    const int cnt = g_counts[e];
    const int m0  = blockIdx.y * 128;
    if (m0 >= cnt) return;
    const int n0i = blockIdx.x * 64;

    extern __shared__ char sm[];
    const uint32_t smb = smem_u32(sm);
    const int tid = threadIdx.x, wid = tid >> 5, lane = tid & 31;
    const int lr = lane >> 2, lc = lane & 3;
    const int wm = (wid & 3) * 32, wn = (wid >> 2) * 32;
    int* sTok = (int*)sm;

    if (tid < 128) { int s = m0 + tid; sTok[tid] = (s < cnt) ? g_tok[e * NT + s] : 0; }
    __syncthreads();

    float acc[2][8][4];
#pragma unroll
    for (int mt = 0; mt < 2; ++mt)
#pragma unroll
        for (int nt = 0; nt < 8; ++nt)
#pragma unroll
            for (int i = 0; i < 4; ++i) acc[mt][nt][i] = 0.f;

    const int ar = tid >> 3,  ac = tid & 7;     // A loader: rows ar+32i, 16B chunk ac
    const int br = tid >> 4,  bc = tid & 15;    // B loader: rows br+16i, float4 chunk bc

    const uint32_t aoff = (uint32_t)((wm + (lane & 15)) * RSTRIDE + (lane >> 4) * 16);
    const uint32_t boff = (uint32_t)(((lane & 7) + ((lane >> 4) << 3)) * RSTRIDE
                                     + ((lane >> 3) & 1) * 16);

    float4 b4[8];
    // ---- prologue: A(0) via cp.async; B(0) LDG->STS; B(1) LDG
#pragma unroll
    for (int i = 0; i < 4; ++i) {
        int r = ar + i * 32;
        cpa16(smb + OFF_A(0) + r * RSTRIDE + ac * 16,
              g_x16 + (size_t)sTok[r] * NH + ac * 8);
    }
    cp_commit();
#pragma unroll
    for (int i = 0; i < 8; ++i) {
        int r = br + i * 16;
        int grow = (r < 64) ? (n0i + r) : (2048 + n0i + r - 64);
        b4[i] = *(const float4*)(w13 + ((size_t)e * 4096 + grow) * NH + bc * 4);
    }
#pragma unroll
    for (int i = 0; i < 8; ++i) {
        int r = br + i * 16;
        uint2 p = make_uint2(pkh2(b4[i].x, b4[i].y), pkh2(b4[i].z, b4[i].w));
        *(uint2*)(sm + OFF_B(0) + r * RSTRIDE + bc * 8) = p;
    }
#pragma unroll
    for (int i = 0; i < 8; ++i) {
        int r = br + i * 16;
        int grow = (r < 64) ? (n0i + r) : (2048 + n0i + r - 64);
        b4[i] = *(const float4*)(w13 + ((size_t)e * 4096 + grow) * NH + 64 + bc * 4);
    }
    cp_wait<0>();
    __syncthreads();

#pragma unroll 1
    for (int s = 0; s < 16; ++s) {
        const int cur = s & 1;
        const uint32_t stA = OFF_A(cur), stB = OFF_B(cur);
        // fill alt buffer (safe: alt was last read at stage s-1, barrier passed)
        if (s < 15) {
            const int k0n = (s + 1) * 64;
#pragma unroll
            for (int i = 0; i < 4; ++i) {
                int r = ar + i * 32;
                cpa16(smb + OFF_A(cur ^ 1) + r * RSTRIDE + ac * 16,
                      g_x16 + (size_t)sTok[r] * NH + k0n + ac * 8);
            }
            cp_commit();
#pragma unroll
            for (int i = 0; i < 8; ++i) {
                int r = br + i * 16;
                uint2 p = make_uint2(pkh2(b4[i].x, b4[i].y), pkh2(b4[i].z, b4[i].w));
                *(uint2*)(sm + OFF_B(cur ^ 1) + r * RSTRIDE + bc * 8) = p;
            }
        }
        if (s < 14) {
            const int k0n2 = (s + 2) * 64;
#pragma unroll
            for (int i = 0; i < 8; ++i) {
                int r = br + i * 16;
                int grow = (r < 64) ? (n0i + r) : (2048 + n0i + r - 64);
                b4[i] = *(const float4*)(w13 + ((size_t)e * 4096 + grow) * NH + k0n2 + bc * 4);
            }
        }
        // compute current buffer
#pragma unroll
        for (int k16 = 0; k16 < 4; ++k16) {
            uint32_t a[2][4];
            uint32_t abase = smb + stA + aoff + k16 * 32;
            ldm4(a[0], abase);
            ldm4(a[1], abase + 16 * RSTRIDE);
#pragma unroll
            for (int ntp = 0; ntp < 4; ++ntp) {
                int browoff = ((ntp >= 2) ? 64 : 0) + wn + ((ntp & 1) << 4);
                uint32_t b[4];
                ldm4(b, smb + stB + boff + browoff * RSTRIDE + k16 * 32);
                mma16(acc[0][ntp * 2],     a[0], b);
                mma16(acc[1][ntp * 2],     a[1], b);
                mma16(acc[0][ntp * 2 + 1], a[0], b + 2);
                mma16(acc[1][ntp * 2 + 1], a[1], b + 2);
            }
        }
        if (s < 15) cp_wait<0>();
        __syncthreads();
    }

    // ---- epilogue: SwiGLU in registers, stage act tile in smem, coalesced store
    const float* bg = b13 + (size_t)e * 4096 + n0i;
    const float* bl = b13 + (size_t)e * 4096 + 2048 + n0i;
#pragma unroll
    for (int mt = 0; mt < 2; ++mt)
#pragma unroll
        for (int nt = 0; nt < 4; ++nt)
#pragma unroll
            for (int i = 0; i < 2; ++i) {
                int row = wm + mt * 16 + lr + i * 8;
                int col = wn + nt * 8 + lc * 2;
                float g0 = acc[mt][nt][i * 2 + 0] + bg[col];
                float g1 = acc[mt][nt][i * 2 + 1] + bg[col + 1];
                float l0 = acc[mt][nt + 4][i * 2 + 0] + bl[col];
                float l1 = acc[mt][nt + 4][i * 2 + 1] + bl[col + 1];
                float a0 = g0 * (1.f / (1.f + __expf(-1.702f * g0))) * (l0 + 1.0f);
                float a1 = g1 * (1.f / (1.f + __expf(-1.702f * g1))) * (l1 + 1.0f);
                *(uint32_t*)(sm + 1024 + row * RSTRIDE + col * 2) = pkh2(a0, a1);
            }
    __syncthreads();
#pragma unroll
    for (int i = 0; i < 4; ++i) {
        int idx = i * 256 + tid;
        int r = idx >> 3, c = idx & 7;
        int slot = m0 + r;
        if (slot < cnt) {
            uint4 v = *(uint4*)(sm + 1024 + r * RSTRIDE + c * 16);
            *(uint4*)(g_act + ((size_t)e * NT + slot) * NI + n0i + c * 8) = v;
        }
    }
}

// ---------------- GEMM2: y = act @ w2^T, gated atomic scatter ----------------
// CTA: 128 slots x 128 out cols; same single-barrier pipeline, S=32.
__global__ __launch_bounds__(256, 2)
void gemm2_k(const float* __restrict__ w2, const float* __restrict__ b2,
             float* __restrict__ out) {
    const int e   = blockIdx.z;
    const int cnt = g_counts[e];
    const int m0  = blockIdx.y * 128;
    if (m0 >= cnt) return;
    const int n0  = blockIdx.x * 128;

    extern __shared__ char sm[];
    const uint32_t smb = smem_u32(sm);
    const int tid = threadIdx.x, wid = tid >> 5, lane = tid & 31;
    const int lr = lane >> 2, lc = lane & 3;
    const int wm = (wid & 3) * 32, wn = (wid >> 2) * 64;
    int*   sTok = (int*)sm;
    float* sG   = (float*)(sm + 512);

    if (tid < 128) {
        int slot = m0 + tid;
        sTok[tid] = (slot < cnt) ? g_tok[e * NT + slot] : 0;
        sG[tid]   = (slot < cnt) ? g_gate[e * NT + slot] : 0.f;
    }
    __syncthreads();

    float acc[2][8][4];
#pragma unroll
    for (int mt = 0; mt < 2; ++mt)
#pragma unroll
        for (int nt = 0; nt < 8; ++nt)
#pragma unroll
            for (int i = 0; i < 4; ++i) acc[mt][nt][i] = 0.f;

    const int ar = tid >> 3,  ac = tid & 7;
    const int br = tid >> 4,  bc = tid & 15;
    const uint32_t aoff = (uint32_t)((wm + (lane & 15)) * RSTRIDE + (lane >> 4) * 16);
    const uint32_t boff = (uint32_t)(((lane & 7) + ((lane >> 4) << 3)) * RSTRIDE
                                     + ((lane >> 3) & 1) * 16);

    float4 b4[8];
    // ---- prologue
#pragma unroll
    for (int i = 0; i < 4; ++i) {
        int r = ar + i * 32;
        cpa16(smb + OFF_A(0) + r * RSTRIDE + ac * 16,
              g_act + ((size_t)e * NT + m0 + r) * NI + ac * 8);
    }
    cp_commit();
#pragma unroll
    for (int i = 0; i < 8; ++i) {
        int r = br + i * 16;
        b4[i] = *(const float4*)(w2 + ((size_t)e * NH + n0 + r) * NI + bc * 4);
    }
#pragma unroll
    for (int i = 0; i < 8; ++i) {
        int r = br + i * 16;
        uint2 p = make_uint2(pkh2(b4[i].x, b4[i].y), pkh2(b4[i].z, b4[i].w));
        *(uint2*)(sm + OFF_B(0) + r * RSTRIDE + bc * 8) = p;
    }
#pragma unroll
    for (int i = 0; i < 8; ++i) {
        int r = br + i * 16;
        b4[i] = *(const float4*)(w2 + ((size_t)e * NH + n0 + r) * NI + 64 + bc * 4);
    }
    cp_wait<0>();
    __syncthreads();

#pragma unroll 1
    for (int s = 0; s < 32; ++s) {
        const int cur = s & 1;
        const uint32_t stA = OFF_A(cur), stB = OFF_B(cur);
        if (s < 31) {
            const int k0n = (s + 1) * 64;
#pragma unroll
            for (int i = 0; i < 4; ++i) {
                int r = ar + i * 32;
                cpa16(smb + OFF_A(cur ^ 1) + r * RSTRIDE + ac * 16,
                      g_act + ((size_t)e * NT + m0 + r) * NI + k0n + ac * 8);
            }
            cp_commit();
#pragma unroll
            for (int i = 0; i < 8; ++i) {
                int r = br + i * 16;
                uint2 p = make_uint2(pkh2(b4[i].x, b4[i].y), pkh2(b4[i].z, b4[i].w));
                *(uint2*)(sm + OFF_B(cur ^ 1) + r * RSTRIDE + bc * 8) = p;
            }
        }
        if (s < 30) {
            const int k0n2 = (s + 2) * 64;
#pragma unroll
            for (int i = 0; i < 8; ++i) {
                int r = br + i * 16;
                b4[i] = *(const float4*)(w2 + ((size_t)e * NH + n0 + r) * NI + k0n2 + bc * 4);
            }
        }
#pragma unroll
        for (int k16 = 0; k16 < 4; ++k16) {
            uint32_t a[2][4];
            uint32_t abase = smb + stA + aoff + k16 * 32;
            ldm4(a[0], abase);
            ldm4(a[1], abase + 16 * RSTRIDE);
#pragma unroll
            for (int ntp = 0; ntp < 4; ++ntp) {
                uint32_t b[4];
                ldm4(b, smb + stB + boff + (wn + ntp * 16) * RSTRIDE + k16 * 32);
                mma16(acc[0][ntp * 2],     a[0], b);
                mma16(acc[1][ntp * 2],     a[1], b);
                mma16(acc[0][ntp * 2 + 1], a[0], b + 2);
                mma16(acc[1][ntp * 2 + 1], a[1], b + 2);
            }
        }
        if (s < 31) cp_wait<0>();
        __syncthreads();
    }

    // epilogue: out[tok, n0+col] += gate * (acc + b2)
    const float* bb = b2 + (size_t)e * NH + n0;
#pragma unroll
    for (int mt = 0; mt < 2; ++mt)
#pragma unroll
        for (int i = 0; i < 2; ++i) {
            int row = wm + mt * 16 + lr + i * 8;
            int slot = m0 + row;
            if (slot >= cnt) continue;
            int tok = sTok[row];
            float gate = sG[row];
            float* orow = out + (size_t)tok * NH + n0;
#pragma unroll
            for (int nt = 0; nt < 8; ++nt) {
                int col = wn + nt * 8 + lc * 2;
                atomicAdd(orow + col,     gate * (acc[mt][nt][i * 2 + 0] + bb[col]));
                atomicAdd(orow + col + 1, gate * (acc[mt][nt][i * 2 + 1] + bb[col + 1]));
            }
        }
}

// ---------------- host entry ----------------
extern "C" void kernel_launch(void* const* d_in, const int* in_sizes, int n_in,
                              void* d_out, int out_size) {
    const float* x      = (const float*)d_in[0];
    const float* logits = (const float*)d_in[1];
    const float* w13    = (const float*)d_in[2];
    const float* w2     = (const float*)d_in[3];
    const float* b13    = (const float*)d_in[4];
    const float* b2     = (const float*)d_in[5];
    float* out          = (float*)d_out;

    cudaFuncSetAttribute(gemm1_k, cudaFuncAttributeMaxDynamicSharedMemorySize, SMEM_TOT);
    cudaFuncSetAttribute(gemm2_k, cudaFuncAttributeMaxDynamicSharedMemorySize, SMEM_TOT);

    prep_kernel<<<(NT * NH + 255) / 256, 256>>>(x, out);
    router_kernel<<<(NT + 255) / 256, 256>>>(logits);
    gemm1_k<<<dim3(NI / 64, NT / 128, NE), 256, SMEM_TOT>>>(w13, b13);
    gemm2_k<<<dim3(NH / 128, NT / 128, NE), 256, SMEM_TOT>>>(w2, b2, out);
}